// round 13
// baseline (speedup 1.0000x reference)
#include <cuda_runtime.h>
#include <cuda_bf16.h>
#include <cstdint>
#include <cstddef>

// ---------------- problem constants ----------------
#define CTXLEN 77
#define WIDTH  512
#define HEADS  8
#define DHEAD  64
#define LAYERS 12
#define EMBED  1024
#define NSEQ   128
#define PPROMPT 8
#define LPROM  16
#define EOTTOK 49407
#define BATCH  (PPROMPT*NSEQ)          /* 1024 */

// compacted layout: shared prefix (computed once across P) + prompt windows
#define SHSTRIDE 61
#define SHTOT (NSEQ*SHSTRIDE)          /* 7808  */
#define PRTOT (BATCH*LPROM)            /* 16384 */
#define MTOT  (SHTOT+PRTOT)            /* 24192 = 189*128 */

// ---------------- device scratch ----------------
__device__ float g_h   [(size_t)MTOT*WIDTH];
__device__ float g_y   [(size_t)MTOT*WIDTH];
__device__ float g_attn[(size_t)MTOT*WIDTH];
__device__ float g_qkv [(size_t)MTOT*3*WIDTH];
__device__ float g_ffn [(size_t)MTOT*4*WIDTH];
__device__ int   g_posy[NSEQ];
__device__ float g_fy  [(size_t)BATCH*WIDTH];
__device__ float g_feats[(size_t)BATCH*EMBED];

// ================= helpers =================
__device__ __forceinline__ uint32_t smem_u32(const void* p) {
    uint32_t a;
    asm("{ .reg .u64 t; cvta.to.shared.u64 t, %1; cvt.u32.u64 %0, t; }" : "=r"(a) : "l"(p));
    return a;
}
__device__ __forceinline__ void cp_async16(uint32_t s, const void* g) {
    asm volatile("cp.async.cg.shared.global [%0], [%1], 16;" :: "r"(s), "l"(g));
}
#define CP_COMMIT() asm volatile("cp.async.commit_group;" ::: "memory")

__device__ __forceinline__ void mma_tf32(float* d, const uint32_t* a, const uint32_t* b) {
    asm volatile(
        "mma.sync.aligned.m16n8k8.row.col.f32.tf32.tf32.f32 "
        "{%0,%1,%2,%3}, {%4,%5,%6,%7}, {%8,%9}, {%0,%1,%2,%3};"
        : "+f"(d[0]), "+f"(d[1]), "+f"(d[2]), "+f"(d[3])
        : "r"(a[0]), "r"(a[1]), "r"(a[2]), "r"(a[3]), "r"(b[0]), "r"(b[1]));
}

#define ROWSTRIDE 40
#define TILEF (128*ROWSTRIDE)
#define STAGEF (2*TILEF)
#define MMA_SMEM_BYTES (2*STAGEF*4)    /* 81920 bytes */

// ================= 8-warp GEMM (64x32 per warp) — out/proj shapes ===========
template<int EPI>
__launch_bounds__(256, 2)
__global__ void mma_gemm(const float* __restrict__ A, const float* __restrict__ B,
                         const float* __restrict__ bias, const float* __restrict__ res,
                         float* __restrict__ C, int M, int N, int K)
{
    extern __shared__ __align__(16) float sm[];
    const int tid  = threadIdx.x;
    const int lane = tid & 31, wid = tid >> 5;
    const int wm = wid & 1, wn = wid >> 1;     // 2 x 4 warps, 64x32 each
    const int m0 = blockIdx.y * 128, n0 = blockIdx.x * 128;
    const uint32_t sbase = smem_u32(sm);

    auto stage = [&](int s, int k0) {
        #pragma unroll
        for (int i = 0; i < 4; i++) {
            int ch  = tid + i*256;
            int row = ch >> 3;
            int cc  = (ch & 7) << 2;
            uint32_t so = sbase + (uint32_t)(s*STAGEF + row*ROWSTRIDE + cc)*4u;
            cp_async16(so,            A + (size_t)(m0+row)*K + k0 + cc);
            cp_async16(so + TILEF*4u, B + (size_t)(n0+row)*K + k0 + cc);
        }
        CP_COMMIT();
    };

    float acc[4][4][4];
    #pragma unroll
    for (int mt = 0; mt < 4; mt++)
        #pragma unroll
        for (int nt = 0; nt < 4; nt++)
            #pragma unroll
            for (int q = 0; q < 4; q++) acc[mt][nt][q] = 0.f;

    const int nk = K >> 5;
    stage(0, 0);
    stage(1, 32);

    const int r = lane >> 2, c = lane & 3;
    for (int i = 0; i < nk; i++) {
        if (i == nk - 1) asm volatile("cp.async.wait_group 0;" ::: "memory");
        else             asm volatile("cp.async.wait_group 1;" ::: "memory");
        __syncthreads();
        const float* As = sm + (i & 1)*STAGEF;
        const float* Bs = As + TILEF;
        #pragma unroll
        for (int ks = 0; ks < 4; ks++) {
            uint32_t a[4][4], b[4][2];
            #pragma unroll
            for (int mt = 0; mt < 4; mt++) {
                const float* p0 = As + (wm*64 + mt*16 + r)*ROWSTRIDE + ks*8 + 2*c;
                float2 v0 = *(const float2*)p0;
                float2 v1 = *(const float2*)(p0 + 8*ROWSTRIDE);
                a[mt][0] = __float_as_uint(v0.x);
                a[mt][2] = __float_as_uint(v0.y);
                a[mt][1] = __float_as_uint(v1.x);
                a[mt][3] = __float_as_uint(v1.y);
            }
            #pragma unroll
            for (int nt = 0; nt < 4; nt++) {
                const float* p = Bs + (wn*32 + nt*8 + r)*ROWSTRIDE + ks*8 + 2*c;
                float2 v = *(const float2*)p;
                b[nt][0] = __float_as_uint(v.x);
                b[nt][1] = __float_as_uint(v.y);
            }
            #pragma unroll
            for (int mt = 0; mt < 4; mt++)
                #pragma unroll
                for (int nt = 0; nt < 4; nt++)
                    mma_tf32(acc[mt][nt], a[mt], b[nt]);
        }
        __syncthreads();
        if (i + 2 < nk) stage(i & 1, (i + 2)*32);
    }

    #pragma unroll
    for (int mt = 0; mt < 4; mt++) {
        int row0 = m0 + wm*64 + mt*16 + r;
        #pragma unroll
        for (int nt = 0; nt < 4; nt++) {
            int col = n0 + wn*32 + nt*8 + 2*c;
            float b0 = bias[col], b1 = bias[col + 1];
            float2 v0, v1;
            v0.x = acc[mt][nt][0] + b0; v0.y = acc[mt][nt][1] + b1;
            v1.x = acc[mt][nt][2] + b0; v1.y = acc[mt][nt][3] + b1;
            if (EPI == 1) {
                v0.x = v0.x / (1.f + __expf(-1.702f*v0.x));
                v0.y = v0.y / (1.f + __expf(-1.702f*v0.y));
                v1.x = v1.x / (1.f + __expf(-1.702f*v1.x));
                v1.y = v1.y / (1.f + __expf(-1.702f*v1.y));
            }
            if (EPI == 2) {
                float2 r0 = *(const float2*)(res + (size_t)row0*N + col);
                float2 r1 = *(const float2*)(res + (size_t)(row0+8)*N + col);
                v0.x += r0.x; v0.y += r0.y; v1.x += r1.x; v1.y += r1.y;
            }
            *(float2*)(C + (size_t)row0*N + col)     = v0;
            *(float2*)(C + (size_t)(row0+8)*N + col) = v1;
        }
    }
}

// ================= 4-warp GEMM (64x64 per warp) — qkv/fc shapes =============
template<int EPI>
__launch_bounds__(128, 2)
__global__ void mma_gemm4(const float* __restrict__ A, const float* __restrict__ B,
                          const float* __restrict__ bias, const float* __restrict__ res,
                          float* __restrict__ C, int M, int N, int K)
{
    extern __shared__ __align__(16) float sm[];
    const int tid  = threadIdx.x;              // 128
    const int lane = tid & 31, wid = tid >> 5; // 4 warps
    const int wm = wid & 1, wn = wid >> 1;     // 2 x 2 warps, 64x64 each
    const int m0 = blockIdx.y * 128, n0 = blockIdx.x * 128;
    const uint32_t sbase = smem_u32(sm);

    auto stage = [&](int s, int k0) {
        #pragma unroll
        for (int i = 0; i < 8; i++) {
            int ch  = tid + i*128;             // 0..1023
            int row = ch >> 3;
            int cc  = (ch & 7) << 2;
            uint32_t so = sbase + (uint32_t)(s*STAGEF + row*ROWSTRIDE + cc)*4u;
            cp_async16(so,            A + (size_t)(m0+row)*K + k0 + cc);
            cp_async16(so + TILEF*4u, B + (size_t)(n0+row)*K + k0 + cc);
        }
        CP_COMMIT();
    };

    float acc[4][8][4];
    #pragma unroll
    for (int mt = 0; mt < 4; mt++)
        #pragma unroll
        for (int nt = 0; nt < 8; nt++)
            #pragma unroll
            for (int q = 0; q < 4; q++) acc[mt][nt][q] = 0.f;

    const int nk = K >> 5;
    stage(0, 0);
    stage(1, 32);

    const int r = lane >> 2, c = lane & 3;
    for (int i = 0; i < nk; i++) {
        if (i == nk - 1) asm volatile("cp.async.wait_group 0;" ::: "memory");
        else             asm volatile("cp.async.wait_group 1;" ::: "memory");
        __syncthreads();
        const float* As = sm + (i & 1)*STAGEF;
        const float* Bs = As + TILEF;
        #pragma unroll
        for (int ks = 0; ks < 4; ks++) {
            uint32_t a[4][4], b[8][2];
            #pragma unroll
            for (int mt = 0; mt < 4; mt++) {
                const float* p0 = As + (wm*64 + mt*16 + r)*ROWSTRIDE + ks*8 + 2*c;
                float2 v0 = *(const float2*)p0;
                float2 v1 = *(const float2*)(p0 + 8*ROWSTRIDE);
                a[mt][0] = __float_as_uint(v0.x);
                a[mt][2] = __float_as_uint(v0.y);
                a[mt][1] = __float_as_uint(v1.x);
                a[mt][3] = __float_as_uint(v1.y);
            }
            #pragma unroll
            for (int nt = 0; nt < 8; nt++) {
                const float* p = Bs + (wn*64 + nt*8 + r)*ROWSTRIDE + ks*8 + 2*c;
                float2 v = *(const float2*)p;
                b[nt][0] = __float_as_uint(v.x);
                b[nt][1] = __float_as_uint(v.y);
            }
            #pragma unroll
            for (int mt = 0; mt < 4; mt++)
                #pragma unroll
                for (int nt = 0; nt < 8; nt++)
                    mma_tf32(acc[mt][nt], a[mt], b[nt]);
        }
        __syncthreads();
        if (i + 2 < nk) stage(i & 1, (i + 2)*32);
    }

    #pragma unroll
    for (int mt = 0; mt < 4; mt++) {
        int row0 = m0 + wm*64 + mt*16 + r;
        #pragma unroll
        for (int nt = 0; nt < 8; nt++) {
            int col = n0 + wn*64 + nt*8 + 2*c;
            float b0 = bias[col], b1 = bias[col + 1];
            float2 v0, v1;
            v0.x = acc[mt][nt][0] + b0; v0.y = acc[mt][nt][1] + b1;
            v1.x = acc[mt][nt][2] + b0; v1.y = acc[mt][nt][3] + b1;
            if (EPI == 1) {
                v0.x = v0.x / (1.f + __expf(-1.702f*v0.x));
                v0.y = v0.y / (1.f + __expf(-1.702f*v0.y));
                v1.x = v1.x / (1.f + __expf(-1.702f*v1.x));
                v1.y = v1.y / (1.f + __expf(-1.702f*v1.y));
            }
            if (EPI == 2) {
                float2 r0 = *(const float2*)(res + (size_t)row0*N + col);
                float2 r1 = *(const float2*)(res + (size_t)(row0+8)*N + col);
                v0.x += r0.x; v0.y += r0.y; v1.x += r1.x; v1.y += r1.y;
            }
            *(float2*)(C + (size_t)row0*N + col)     = v0;
            *(float2*)(C + (size_t)(row0+8)*N + col) = v1;
        }
    }
}

// ---------------- pos_y ----------------
__global__ void posy_kernel(const int* __restrict__ text, int* __restrict__ posy)
{
    int n = threadIdx.x;
    if (n < NSEQ) {
        int p = 0;
        for (int t = 0; t < CTXLEN; t++) {
            if (text[n*CTXLEN + t] == EOTTOK) { p = t; break; }
        }
        posy[n] = p;
    }
}

// ---------------- embedding into the compacted layout ----------------
__global__ void embed_kernel(const int* __restrict__ text,
                             const float* __restrict__ cprompt,
                             const float* __restrict__ tok,
                             const float* __restrict__ pos,
                             const int* __restrict__ posy,
                             float* __restrict__ h)
{
    int row = blockIdx.x;
    int d = threadIdx.x * 4;
    float4 v;
    if (row < SHTOT) {
        int n = row / SHSTRIDE, t = row % SHSTRIDE;
        int py = posy[n];
        if (t >= py) {
            *(float4*)(h + (size_t)row*WIDTH + d) = make_float4(0.f,0.f,0.f,0.f);
            return;
        }
        const float* src = tok + (size_t)text[n*CTXLEN + t]*WIDTH;
        float4 s = *(const float4*)(src + d);
        float4 pe = *(const float4*)(pos + (size_t)t*WIDTH + d);
        v.x = s.x + pe.x; v.y = s.y + pe.y; v.z = s.z + pe.z; v.w = s.w + pe.w;
    } else {
        int q = row - SHTOT;
        int j = q & (LPROM-1), pn = q >> 4;
        int p = pn >> 7, n = pn & (NSEQ-1);
        int t = posy[n] + j;
        float4 s = *(const float4*)(cprompt + ((size_t)p*LPROM + j)*WIDTH + d);
        float4 pe = *(const float4*)(pos + (size_t)t*WIDTH + d);
        v.x = s.x + pe.x; v.y = s.y + pe.y; v.z = s.z + pe.z; v.w = s.w + pe.w;
    }
    *(float4*)(h + (size_t)row*WIDTH + d) = v;
}

// ---------------- layernorm ----------------
__device__ __forceinline__ void ln_row(const float* __restrict__ xr,
                                       const float* __restrict__ w,
                                       const float* __restrict__ b,
                                       float* __restrict__ yr)
{
    int tid = threadIdx.x;               // 128
    float4 v = *(const float4*)(xr + tid*4);
    float s  = v.x + v.y + v.z + v.w;
    float sq = v.x*v.x + v.y*v.y + v.z*v.z + v.w*v.w;
    __shared__ float rs[4], rq[4];
    #pragma unroll
    for (int o = 16; o; o >>= 1) {
        s  += __shfl_xor_sync(0xffffffffu, s,  o);
        sq += __shfl_xor_sync(0xffffffffu, sq, o);
    }
    if ((tid & 31) == 0) { rs[tid>>5] = s; rq[tid>>5] = sq; }
    __syncthreads();
    s  = rs[0]+rs[1]+rs[2]+rs[3];
    sq = rq[0]+rq[1]+rq[2]+rq[3];
    float mean = s * (1.f/WIDTH);
    float var  = sq * (1.f/WIDTH) - mean*mean;
    float rstd = rsqrtf(var + 1e-5f);
    float4 wv = *(const float4*)(w + tid*4);
    float4 bv = *(const float4*)(b + tid*4);
    float4 o;
    o.x = (v.x-mean)*rstd*wv.x + bv.x;
    o.y = (v.y-mean)*rstd*wv.y + bv.y;
    o.z = (v.z-mean)*rstd*wv.z + bv.z;
    o.w = (v.w-mean)*rstd*wv.w + bv.w;
    *(float4*)(yr + tid*4) = o;
}

__global__ void ln_kernel(const float* __restrict__ x, const float* __restrict__ w,
                          const float* __restrict__ b, float* __restrict__ y)
{
    size_t row = blockIdx.x;
    ln_row(x + row*WIDTH, w, b, y + row*WIDTH);
}

__global__ void gatherln_kernel(const float* __restrict__ h, const float* __restrict__ w,
                                const float* __restrict__ b, float* __restrict__ y)
{
    int bn = blockIdx.x;                  // p*NSEQ + n
    size_t row = (size_t)SHTOT + (size_t)bn*LPROM + (LPROM - 1);
    ln_row(h + row*WIDTH, w, b, y + (size_t)bn*WIDTH);
}

// ---------------- attention over the shared prefix (per (n,h)) -------------
__launch_bounds__(256)
__global__ void attn_prefix_kernel(const float* __restrict__ qkv,
                                   const int* __restrict__ posy,
                                   float* __restrict__ out)
{
    int bh = blockIdx.x;               // n*8 + h
    int h = bh & 7, n = bh >> 3;
    int py = posy[n];
    __shared__ float Ks[SHSTRIDE][65];
    __shared__ float Vs[SHSTRIDE][65];
    __shared__ float qs[8][64];
    __shared__ float sc[8][64];
    int tid = threadIdx.x, w = tid >> 5, lane = tid & 31;
    const float* base = qkv + (size_t)(n*SHSTRIDE)*(3*WIDTH) + h*DHEAD;

    for (int idx = tid; idx < py*16; idx += 256) {
        int m = idx >> 4, c4 = (idx & 15) << 2;
        float4 kv = *(const float4*)(base + (size_t)m*(3*WIDTH) + WIDTH   + c4);
        Ks[m][c4+0] = kv.x; Ks[m][c4+1] = kv.y; Ks[m][c4+2] = kv.z; Ks[m][c4+3] = kv.w;
        float4 vv = *(const float4*)(base + (size_t)m*(3*WIDTH) + 2*WIDTH + c4);
        Vs[m][c4+0] = vv.x; Vs[m][c4+1] = vv.y; Vs[m][c4+2] = vv.z; Vs[m][c4+3] = vv.w;
    }
    __syncthreads();

    for (int l = w; l < py; l += 8) {
        qs[w][lane]      = base[(size_t)l*(3*WIDTH) + lane];
        qs[w][lane + 32] = base[(size_t)l*(3*WIDTH) + lane + 32];
        __syncwarp();

        float sloc[2];
        float mx = -1e30f;
        #pragma unroll
        for (int rr = 0; rr < 2; rr++) {
            int m = lane + rr*32;
            float s = -1e30f;
            if (m <= l) {
                float dot = 0.f;
                #pragma unroll
                for (int d = 0; d < 64; d++) dot = fmaf(qs[w][d], Ks[m][d], dot);
                s = dot * 0.125f;
            }
            sloc[rr] = s;
            mx = fmaxf(mx, s);
        }
        #pragma unroll
        for (int o = 16; o; o >>= 1) mx = fmaxf(mx, __shfl_xor_sync(0xffffffffu, mx, o));

        float sum = 0.f;
        #pragma unroll
        for (int rr = 0; rr < 2; rr++) {
            int m = lane + rr*32;
            if (m <= l) {
                float e = __expf(sloc[rr] - mx);
                sc[w][m] = e;
                sum += e;
            }
        }
        #pragma unroll
        for (int o = 16; o; o >>= 1) sum += __shfl_xor_sync(0xffffffffu, sum, o);
        float inv = 1.f / sum;

        float o0 = 0.f, o1 = 0.f;
        for (int m = 0; m <= l; m++) {
            float pm = sc[w][m];
            o0 = fmaf(pm, Vs[m][lane],      o0);
            o1 = fmaf(pm, Vs[m][lane + 32], o1);
        }
        float* op = out + ((size_t)n*SHSTRIDE + l)*WIDTH + h*DHEAD;
        op[lane]      = o0 * inv;
        op[lane + 32] = o1 * inv;
        __syncwarp();
    }
}

// ---------------- attention for prompt windows (per (p,n,h)) ----------------
__launch_bounds__(256)
__global__ void attn_prompt_kernel(const float* __restrict__ qkv,
                                   const int* __restrict__ posy,
                                   float* __restrict__ out)
{
    int bh = blockIdx.x;               // pn*8 + h
    int h = bh & 7, pn = bh >> 3;
    int n = pn & (NSEQ-1);
    int py = posy[n];
    __shared__ float Ks[CTXLEN][65];
    __shared__ float Vs[CTXLEN][65];
    __shared__ float qs[8][64];
    __shared__ float sc[8][80];
    int tid = threadIdx.x, w = tid >> 5, lane = tid & 31;
    const float* shbase = qkv + (size_t)(n*SHSTRIDE)*(3*WIDTH) + h*DHEAD;
    const float* prbase = qkv + ((size_t)SHTOT + (size_t)pn*LPROM)*(3*WIDTH) + h*DHEAD;

    int L = py + LPROM;
    for (int idx = tid; idx < L*16; idx += 256) {
        int m = idx >> 4, c4 = (idx & 15) << 2;
        const float* src = (m < py) ? (shbase + (size_t)m*(3*WIDTH))
                                    : (prbase + (size_t)(m - py)*(3*WIDTH));
        float4 kv = *(const float4*)(src + WIDTH   + c4);
        Ks[m][c4+0] = kv.x; Ks[m][c4+1] = kv.y; Ks[m][c4+2] = kv.z; Ks[m][c4+3] = kv.w;
        float4 vv = *(const float4*)(src + 2*WIDTH + c4);
        Vs[m][c4+0] = vv.x; Vs[m][c4+1] = vv.y; Vs[m][c4+2] = vv.z; Vs[m][c4+3] = vv.w;
    }
    __syncthreads();

    for (int j = w; j < LPROM; j += 8) {
        const float* qrow = prbase + (size_t)j*(3*WIDTH);
        qs[w][lane]      = qrow[lane];
        qs[w][lane + 32] = qrow[lane + 32];
        __syncwarp();

        int klen = py + j + 1;
        float sloc[3];
        float mx = -1e30f;
        #pragma unroll
        for (int rr = 0; rr < 3; rr++) {
            int m = lane + rr*32;
            float s = -1e30f;
            if (m < klen) {
                float dot = 0.f;
                #pragma unroll
                for (int d = 0; d < 64; d++) dot = fmaf(qs[w][d], Ks[m][d], dot);
                s = dot * 0.125f;
            }
            sloc[rr] = s;
            mx = fmaxf(mx, s);
        }
        #pragma unroll
        for (int o = 16; o; o >>= 1) mx = fmaxf(mx, __shfl_xor_sync(0xffffffffu, mx, o));

        float sum = 0.f;
        #pragma unroll
        for (int rr = 0; rr < 3; rr++) {
            int m = lane + rr*32;
            if (m < klen) {
                float e = __expf(sloc[rr] - mx);
                sc[w][m] = e;
                sum += e;
            }
        }
        #pragma unroll
        for (int o = 16; o; o >>= 1) sum += __shfl_xor_sync(0xffffffffu, sum, o);
        float inv = 1.f / sum;

        float o0 = 0.f, o1 = 0.f;
        for (int m = 0; m < klen; m++) {
            float pm = sc[w][m];
            o0 = fmaf(pm, Vs[m][lane],      o0);
            o1 = fmaf(pm, Vs[m][lane + 32], o1);
        }
        float* op = out + ((size_t)SHTOT + (size_t)pn*LPROM + j)*WIDTH + h*DHEAD;
        op[lane]      = o0 * inv;
        op[lane + 32] = o1 * inv;
        __syncwarp();
    }
}

// ---------------- fp32 SGEMM (text projection only) -----
template<bool BT, int EPI>
__launch_bounds__(256)
__global__ void sgemm(const float* __restrict__ A, const float* __restrict__ Bm,
                      const float* __restrict__ bias, const float* __restrict__ res,
                      float* __restrict__ C, int M, int N, int K)
{
    __shared__ float As[16][132];
    __shared__ float Bs[16][132];
    const int tid = threadIdx.x;
    const int m0 = blockIdx.y * 128;
    const int n0 = blockIdx.x * 128;
    const int tm = (tid >> 4) << 3;
    const int tn = (tid & 15) << 3;
    float acc[8][8];
    #pragma unroll
    for (int i = 0; i < 8; i++)
        #pragma unroll
        for (int j = 0; j < 8; j++) acc[i][j] = 0.f;

    for (int k0 = 0; k0 < K; k0 += 16) {
        #pragma unroll
        for (int i = 0; i < 2; i++) {
            int id  = tid + i*256;
            int row = id >> 2;
            int c4  = (id & 3) << 2;
            float4 v = *(const float4*)(A + (size_t)(m0+row)*K + (k0 + c4));
            As[c4+0][row] = v.x; As[c4+1][row] = v.y;
            As[c4+2][row] = v.z; As[c4+3][row] = v.w;
        }
        if (BT) {
            #pragma unroll
            for (int i = 0; i < 2; i++) {
                int id  = tid + i*256;
                int row = id >> 2;
                int c4  = (id & 3) << 2;
                float4 v = *(const float4*)(Bm + (size_t)(n0+row)*K + (k0 + c4));
                Bs[c4+0][row] = v.x; Bs[c4+1][row] = v.y;
                Bs[c4+2][row] = v.z; Bs[c4+3][row] = v.w;
            }
        } else {
            #pragma unroll
            for (int i = 0; i < 2; i++) {
                int id = tid + i*256;
                int kr = id >> 5;
                int nc = (id & 31) << 2;
                float4 v = *(const float4*)(Bm + (size_t)(k0+kr)*N + (n0 + nc));
                *(float4*)(&Bs[kr][nc]) = v;
            }
        }
        __syncthreads();
        #pragma unroll
        for (int kk = 0; kk < 16; kk++) {
            float a[8], bb[8];
            *(float4*)(a)    = *(const float4*)(&As[kk][tm]);
            *(float4*)(a+4)  = *(const float4*)(&As[kk][tm+4]);
            *(float4*)(bb)   = *(const float4*)(&Bs[kk][tn]);
            *(float4*)(bb+4) = *(const float4*)(&Bs[kk][tn+4]);
            #pragma unroll
            for (int i = 0; i < 8; i++)
                #pragma unroll
                for (int j = 0; j < 8; j++)
                    acc[i][j] = fmaf(a[i], bb[j], acc[i][j]);
        }
        __syncthreads();
    }

    float bv[8];
    #pragma unroll
    for (int j = 0; j < 8; j++) bv[j] = bias ? bias[n0+tn+j] : 0.f;
    #pragma unroll
    for (int i = 0; i < 8; i++) {
        size_t off = (size_t)(m0+tm+i)*N + (n0+tn);
        #pragma unroll
        for (int j = 0; j < 8; j++) {
            float v = acc[i][j] + bv[j];
            if (EPI == 1) v = v / (1.f + __expf(-1.702f*v));
            if (EPI == 2) v += res[off + j];
            C[off + j] = v;
        }
    }
}

// ---------------- per-row L2 normalize ----------------
__global__ void normrows_kernel(float* __restrict__ f)
{
    size_t row = blockIdx.x;
    float* r = f + row*EMBED;
    int tid = threadIdx.x;            // 256
    float4 v = *(float4*)(r + tid*4);
    float sq = v.x*v.x + v.y*v.y + v.z*v.z + v.w*v.w;
    __shared__ float sh[8];
    #pragma unroll
    for (int o = 16; o; o >>= 1) sq += __shfl_xor_sync(0xffffffffu, sq, o);
    if ((tid & 31) == 0) sh[tid>>5] = sq;
    __syncthreads();
    float tot = 0.f;
    #pragma unroll
    for (int i = 0; i < 8; i++) tot += sh[i];
    float inv = rsqrtf(tot);
    v.x *= inv; v.y *= inv; v.z *= inv; v.w *= inv;
    *(float4*)(r + tid*4) = v;
}

// ---------------- mean over N, then normalize ------------------------------
__global__ void meannorm_kernel(const float* __restrict__ f, float* __restrict__ out)
{
    int p = blockIdx.x;                // 8
    int tid = threadIdx.x;             // 256
    float4 a = make_float4(0.f, 0.f, 0.f, 0.f);
    for (int n = 0; n < NSEQ; n++) {
        float4 v = *(const float4*)(f + ((size_t)(p*NSEQ+n))*EMBED + tid*4);
        a.x += v.x; a.y += v.y; a.z += v.z; a.w += v.w;
    }
    const float s = 1.f / NSEQ;
    a.x *= s; a.y *= s; a.z *= s; a.w *= s;
    float sq = a.x*a.x + a.y*a.y + a.z*a.z + a.w*a.w;
    __shared__ float sh[8];
    #pragma unroll
    for (int o = 16; o; o >>= 1) sq += __shfl_xor_sync(0xffffffffu, sq, o);
    if ((tid & 31) == 0) sh[tid>>5] = sq;
    __syncthreads();
    float tot = 0.f;
    #pragma unroll
    for (int i = 0; i < 8; i++) tot += sh[i];
    float inv = rsqrtf(tot);
    a.x *= inv; a.y *= inv; a.z *= inv; a.w *= inv;
    *(float4*)(out + (size_t)p*EMBED + tid*4) = a;
}

// ---------------- host orchestration ---------------------------------------
extern "C" void kernel_launch(void* const* d_in, const int* in_sizes, int n_in,
                              void* d_out, int out_size)
{
    const int*   text  = (const int*)  d_in[0];
    const float* cpr   = (const float*)d_in[1];
    const float* tok   = (const float*)d_in[2];
    const float* pos   = (const float*)d_in[3];
    const float* qkv_w = (const float*)d_in[4];
    const float* qkv_b = (const float*)d_in[5];
    const float* out_w = (const float*)d_in[6];
    const float* out_b = (const float*)d_in[7];
    const float* ln1_w = (const float*)d_in[8];
    const float* ln1_b = (const float*)d_in[9];
    const float* ln2_w = (const float*)d_in[10];
    const float* ln2_b = (const float*)d_in[11];
    const float* fc_w  = (const float*)d_in[12];
    const float* fc_b  = (const float*)d_in[13];
    const float* pj_w  = (const float*)d_in[14];
    const float* pj_b  = (const float*)d_in[15];
    const float* lnf_w = (const float*)d_in[16];
    const float* lnf_b = (const float*)d_in[17];
    const float* tproj = (const float*)d_in[18];
    float* outp = (float*)d_out;
    (void)in_sizes; (void)n_in; (void)out_size;

    void* pv;
    cudaGetSymbolAddress(&pv, g_h);    float* h    = (float*)pv;
    cudaGetSymbolAddress(&pv, g_y);    float* y    = (float*)pv;
    cudaGetSymbolAddress(&pv, g_attn); float* attn = (float*)pv;
    cudaGetSymbolAddress(&pv, g_qkv);  float* qkv  = (float*)pv;
    cudaGetSymbolAddress(&pv, g_ffn);  float* ffn  = (float*)pv;
    cudaGetSymbolAddress(&pv, g_posy); int*   posy = (int*)pv;
    cudaGetSymbolAddress(&pv, g_fy);   float* fy   = (float*)pv;
    cudaGetSymbolAddress(&pv, g_feats);float* fts  = (float*)pv;

    cudaFuncSetAttribute(mma_gemm<0>,  cudaFuncAttributeMaxDynamicSharedMemorySize, MMA_SMEM_BYTES);
    cudaFuncSetAttribute(mma_gemm<1>,  cudaFuncAttributeMaxDynamicSharedMemorySize, MMA_SMEM_BYTES);
    cudaFuncSetAttribute(mma_gemm<2>,  cudaFuncAttributeMaxDynamicSharedMemorySize, MMA_SMEM_BYTES);
    cudaFuncSetAttribute(mma_gemm4<0>, cudaFuncAttributeMaxDynamicSharedMemorySize, MMA_SMEM_BYTES);
    cudaFuncSetAttribute(mma_gemm4<1>, cudaFuncAttributeMaxDynamicSharedMemorySize, MMA_SMEM_BYTES);
    cudaFuncSetAttribute(mma_gemm4<2>, cudaFuncAttributeMaxDynamicSharedMemorySize, MMA_SMEM_BYTES);

    posy_kernel<<<1, 128>>>(text, posy);
    embed_kernel<<<MTOT, 128>>>(text, cpr, tok, pos, posy, h);

    const int GY = MTOT/128;               // 189
    for (int L = 0; L < LAYERS; L++) {
        const float* qw = qkv_w + (size_t)L*3*WIDTH*WIDTH;
        const float* qb = qkv_b + (size_t)L*3*WIDTH;
        const float* ow = out_w + (size_t)L*WIDTH*WIDTH;
        const float* ob = out_b + (size_t)L*WIDTH;
        const float* fw = fc_w  + (size_t)L*4*WIDTH*WIDTH;
        const float* fb = fc_b  + (size_t)L*4*WIDTH;
        const float* pw = pj_w  + (size_t)L*WIDTH*4*WIDTH;
        const float* pb = pj_b  + (size_t)L*WIDTH;

        ln_kernel<<<MTOT, 128>>>(h, ln1_w + L*WIDTH, ln1_b + L*WIDTH, y);
        mma_gemm4<0><<<dim3(3*WIDTH/128, GY), 128, MMA_SMEM_BYTES>>>(
            y, qw, qb, nullptr, qkv, MTOT, 3*WIDTH, WIDTH);
        attn_prefix_kernel<<<NSEQ*HEADS, 256>>>(qkv, posy, attn);
        attn_prompt_kernel<<<BATCH*HEADS, 256>>>(qkv, posy, attn);
        mma_gemm<2><<<dim3(WIDTH/128, GY), 256, MMA_SMEM_BYTES>>>(
            attn, ow, ob, h, h, MTOT, WIDTH, WIDTH);
        ln_kernel<<<MTOT, 128>>>(h, ln2_w + L*WIDTH, ln2_b + L*WIDTH, y);
        mma_gemm4<1><<<dim3(4*WIDTH/128, GY), 128, MMA_SMEM_BYTES>>>(
            y, fw, fb, nullptr, ffn, MTOT, 4*WIDTH, WIDTH);
        mma_gemm<2><<<dim3(WIDTH/128, GY), 256, MMA_SMEM_BYTES>>>(
            ffn, pw, pb, h, h, MTOT, WIDTH, 4*WIDTH);
    }

    gatherln_kernel<<<BATCH, 128>>>(h, lnf_w, lnf_b, fy);
    sgemm<false,0><<<dim3(EMBED/128, BATCH/128), 256>>>(
        fy, tproj, nullptr, nullptr, fts, BATCH, EMBED, WIDTH);
    normrows_kernel<<<BATCH, 256>>>(fts);
    meannorm_kernel<<<PPROMPT, 256>>>(fts, outp);
}

// round 16
// speedup vs baseline: 1.0308x; 1.0308x over previous
#include <cuda_runtime.h>
#include <cuda_bf16.h>
#include <cstdint>
#include <cstddef>

// ---------------- problem constants ----------------
#define CTXLEN 77
#define WIDTH  512
#define HEADS  8
#define DHEAD  64
#define LAYERS 12
#define EMBED  1024
#define NSEQ   128
#define PPROMPT 8
#define LPROM  16
#define EOTTOK 49407
#define BATCH  (PPROMPT*NSEQ)          /* 1024 */

// compacted layout: shared prefix (computed once across P) + prompt windows
#define SHSTRIDE 61
#define SHTOT (NSEQ*SHSTRIDE)          /* 7808  */
#define PRTOT (BATCH*LPROM)            /* 16384 */
#define MTOT  (SHTOT+PRTOT)            /* 24192 = 189*128 */

// ---------------- device scratch ----------------
__device__ float g_h   [(size_t)MTOT*WIDTH];
__device__ float g_y   [(size_t)MTOT*WIDTH];
__device__ float g_attn[(size_t)MTOT*WIDTH];
__device__ float g_qkv [(size_t)MTOT*3*WIDTH];
__device__ float g_ffn [(size_t)MTOT*4*WIDTH];
__device__ int   g_posy[NSEQ];
__device__ float g_fy  [(size_t)BATCH*WIDTH];
__device__ float g_feats[(size_t)BATCH*EMBED];

// ================= helpers =================
__device__ __forceinline__ uint32_t smem_u32(const void* p) {
    uint32_t a;
    asm("{ .reg .u64 t; cvta.to.shared.u64 t, %1; cvt.u32.u64 %0, t; }" : "=r"(a) : "l"(p));
    return a;
}
__device__ __forceinline__ void cp_async16(uint32_t s, const void* g) {
    asm volatile("cp.async.cg.shared.global [%0], [%1], 16;" :: "r"(s), "l"(g));
}
#define CP_COMMIT() asm volatile("cp.async.commit_group;" ::: "memory")

__device__ __forceinline__ void mma_tf32(float* d, const uint32_t* a, const uint32_t* b) {
    asm volatile(
        "mma.sync.aligned.m16n8k8.row.col.f32.tf32.tf32.f32 "
        "{%0,%1,%2,%3}, {%4,%5,%6,%7}, {%8,%9}, {%0,%1,%2,%3};"
        : "+f"(d[0]), "+f"(d[1]), "+f"(d[2]), "+f"(d[3])
        : "r"(a[0]), "r"(a[1]), "r"(a[2]), "r"(a[3]), "r"(b[0]), "r"(b[1]));
}

// ================= mma.sync tf32 GEMM (R7 config, frozen) ===================
#define ROWSTRIDE 40
#define TILEF (128*ROWSTRIDE)
#define STAGEF (2*TILEF)
#define MMA_SMEM_BYTES (2*STAGEF*4)    /* 81920 bytes */

template<int EPI>
__launch_bounds__(256, 2)
__global__ void mma_gemm(const float* __restrict__ A, const float* __restrict__ B,
                         const float* __restrict__ bias, const float* __restrict__ res,
                         float* __restrict__ C, int M, int N, int K)
{
    extern __shared__ __align__(16) float sm[];
    const int tid  = threadIdx.x;
    const int lane = tid & 31, wid = tid >> 5;
    const int wm = wid & 1, wn = wid >> 1;     // 2 x 4 warps, 64x32 each
    const int m0 = blockIdx.y * 128, n0 = blockIdx.x * 128;
    const uint32_t sbase = smem_u32(sm);

    auto stage = [&](int s, int k0) {
        #pragma unroll
        for (int i = 0; i < 4; i++) {
            int ch  = tid + i*256;
            int row = ch >> 3;
            int cc  = (ch & 7) << 2;
            uint32_t so = sbase + (uint32_t)(s*STAGEF + row*ROWSTRIDE + cc)*4u;
            cp_async16(so,            A + (size_t)(m0+row)*K + k0 + cc);
            cp_async16(so + TILEF*4u, B + (size_t)(n0+row)*K + k0 + cc);
        }
        CP_COMMIT();
    };

    float acc[4][4][4];
    #pragma unroll
    for (int mt = 0; mt < 4; mt++)
        #pragma unroll
        for (int nt = 0; nt < 4; nt++)
            #pragma unroll
            for (int q = 0; q < 4; q++) acc[mt][nt][q] = 0.f;

    const int nk = K >> 5;
    stage(0, 0);
    stage(1, 32);

    const int r = lane >> 2, c = lane & 3;
    for (int i = 0; i < nk; i++) {
        if (i == nk - 1) asm volatile("cp.async.wait_group 0;" ::: "memory");
        else             asm volatile("cp.async.wait_group 1;" ::: "memory");
        __syncthreads();
        const float* As = sm + (i & 1)*STAGEF;
        const float* Bs = As + TILEF;
        #pragma unroll
        for (int ks = 0; ks < 4; ks++) {
            uint32_t a[4][4], b[4][2];
            #pragma unroll
            for (int mt = 0; mt < 4; mt++) {
                const float* p0 = As + (wm*64 + mt*16 + r)*ROWSTRIDE + ks*8 + 2*c;
                float2 v0 = *(const float2*)p0;
                float2 v1 = *(const float2*)(p0 + 8*ROWSTRIDE);
                a[mt][0] = __float_as_uint(v0.x);
                a[mt][2] = __float_as_uint(v0.y);
                a[mt][1] = __float_as_uint(v1.x);
                a[mt][3] = __float_as_uint(v1.y);
            }
            #pragma unroll
            for (int nt = 0; nt < 4; nt++) {
                const float* p = Bs + (wn*32 + nt*8 + r)*ROWSTRIDE + ks*8 + 2*c;
                float2 v = *(const float2*)p;
                b[nt][0] = __float_as_uint(v.x);
                b[nt][1] = __float_as_uint(v.y);
            }
            #pragma unroll
            for (int mt = 0; mt < 4; mt++)
                #pragma unroll
                for (int nt = 0; nt < 4; nt++)
                    mma_tf32(acc[mt][nt], a[mt], b[nt]);
        }
        __syncthreads();
        if (i + 2 < nk) stage(i & 1, (i + 2)*32);
    }

    #pragma unroll
    for (int mt = 0; mt < 4; mt++) {
        int row0 = m0 + wm*64 + mt*16 + r;
        #pragma unroll
        for (int nt = 0; nt < 4; nt++) {
            int col = n0 + wn*32 + nt*8 + 2*c;
            float b0 = bias[col], b1 = bias[col + 1];
            float2 v0, v1;
            v0.x = acc[mt][nt][0] + b0; v0.y = acc[mt][nt][1] + b1;
            v1.x = acc[mt][nt][2] + b0; v1.y = acc[mt][nt][3] + b1;
            if (EPI == 1) {
                v0.x = v0.x / (1.f + __expf(-1.702f*v0.x));
                v0.y = v0.y / (1.f + __expf(-1.702f*v0.y));
                v1.x = v1.x / (1.f + __expf(-1.702f*v1.x));
                v1.y = v1.y / (1.f + __expf(-1.702f*v1.y));
            }
            if (EPI == 2) {
                float2 r0 = *(const float2*)(res + (size_t)row0*N + col);
                float2 r1 = *(const float2*)(res + (size_t)(row0+8)*N + col);
                v0.x += r0.x; v0.y += r0.y; v1.x += r1.x; v1.y += r1.y;
            }
            *(float2*)(C + (size_t)row0*N + col)     = v0;
            *(float2*)(C + (size_t)(row0+8)*N + col) = v1;
        }
    }
}

// ---------------- pos_y ----------------
__global__ void posy_kernel(const int* __restrict__ text, int* __restrict__ posy)
{
    int n = threadIdx.x;
    if (n < NSEQ) {
        int p = 0;
        for (int t = 0; t < CTXLEN; t++) {
            if (text[n*CTXLEN + t] == EOTTOK) { p = t; break; }
        }
        posy[n] = p;
    }
}

// ---------------- embedding into the compacted layout ----------------
__global__ void embed_kernel(const int* __restrict__ text,
                             const float* __restrict__ cprompt,
                             const float* __restrict__ tok,
                             const float* __restrict__ pos,
                             const int* __restrict__ posy,
                             float* __restrict__ h)
{
    int row = blockIdx.x;
    int d = threadIdx.x * 4;
    float4 v;
    if (row < SHTOT) {
        int n = row / SHSTRIDE, t = row % SHSTRIDE;
        int py = posy[n];
        if (t >= py) {
            *(float4*)(h + (size_t)row*WIDTH + d) = make_float4(0.f,0.f,0.f,0.f);
            return;
        }
        const float* src = tok + (size_t)text[n*CTXLEN + t]*WIDTH;
        float4 s = *(const float4*)(src + d);
        float4 pe = *(const float4*)(pos + (size_t)t*WIDTH + d);
        v.x = s.x + pe.x; v.y = s.y + pe.y; v.z = s.z + pe.z; v.w = s.w + pe.w;
    } else {
        int q = row - SHTOT;
        int j = q & (LPROM-1), pn = q >> 4;
        int p = pn >> 7, n = pn & (NSEQ-1);
        int t = posy[n] + j;
        float4 s = *(const float4*)(cprompt + ((size_t)p*LPROM + j)*WIDTH + d);
        float4 pe = *(const float4*)(pos + (size_t)t*WIDTH + d);
        v.x = s.x + pe.x; v.y = s.y + pe.y; v.z = s.z + pe.z; v.w = s.w + pe.w;
    }
    *(float4*)(h + (size_t)row*WIDTH + d) = v;
}

// ---------------- layernorm ----------------
__device__ __forceinline__ void ln_row(const float* __restrict__ xr,
                                       const float* __restrict__ w,
                                       const float* __restrict__ b,
                                       float* __restrict__ yr)
{
    int tid = threadIdx.x;               // 128
    float4 v = *(const float4*)(xr + tid*4);
    float s  = v.x + v.y + v.z + v.w;
    float sq = v.x*v.x + v.y*v.y + v.z*v.z + v.w*v.w;
    __shared__ float rs[4], rq[4];
    #pragma unroll
    for (int o = 16; o; o >>= 1) {
        s  += __shfl_xor_sync(0xffffffffu, s,  o);
        sq += __shfl_xor_sync(0xffffffffu, sq, o);
    }
    if ((tid & 31) == 0) { rs[tid>>5] = s; rq[tid>>5] = sq; }
    __syncthreads();
    s  = rs[0]+rs[1]+rs[2]+rs[3];
    sq = rq[0]+rq[1]+rq[2]+rq[3];
    float mean = s * (1.f/WIDTH);
    float var  = sq * (1.f/WIDTH) - mean*mean;
    float rstd = rsqrtf(var + 1e-5f);
    float4 wv = *(const float4*)(w + tid*4);
    float4 bv = *(const float4*)(b + tid*4);
    float4 o;
    o.x = (v.x-mean)*rstd*wv.x + bv.x;
    o.y = (v.y-mean)*rstd*wv.y + bv.y;
    o.z = (v.z-mean)*rstd*wv.z + bv.z;
    o.w = (v.w-mean)*rstd*wv.w + bv.w;
    *(float4*)(yr + tid*4) = o;
}

__global__ void ln_kernel(const float* __restrict__ x, const float* __restrict__ w,
                          const float* __restrict__ b, float* __restrict__ y)
{
    size_t row = blockIdx.x;
    ln_row(x + row*WIDTH, w, b, y + row*WIDTH);
}

__global__ void gatherln_kernel(const float* __restrict__ h, const float* __restrict__ w,
                                const float* __restrict__ b, float* __restrict__ y)
{
    int bn = blockIdx.x;                  // p*NSEQ + n
    size_t row = (size_t)SHTOT + (size_t)bn*LPROM + (LPROM - 1);
    ln_row(h + row*WIDTH, w, b, y + (size_t)bn*WIDTH);
}

// ---------------- attention over the shared prefix (per (n,h)) -------------
// vs R7: Ks stride 65->68 float4 rows, dot loop LDS.128; all smem arrays
// explicitly 16B-aligned (R15 crash root cause).
__launch_bounds__(256)
__global__ void attn_prefix_kernel(const float* __restrict__ qkv,
                                   const int* __restrict__ posy,
                                   float* __restrict__ out)
{
    int bh = blockIdx.x;               // n*8 + h
    int h = bh & 7, n = bh >> 3;
    int py = posy[n];
    __shared__ __align__(16) float Ks[SHSTRIDE][68];
    __shared__ __align__(16) float Vs[SHSTRIDE][65];
    __shared__ __align__(16) float qs[8][64];
    __shared__ __align__(16) float sc[8][64];
    int tid = threadIdx.x, w = tid >> 5, lane = tid & 31;
    const float* base = qkv + (size_t)(n*SHSTRIDE)*(3*WIDTH) + h*DHEAD;

    for (int idx = tid; idx < py*16; idx += 256) {
        int m = idx >> 4, c4 = (idx & 15) << 2;
        *(float4*)&Ks[m][c4] = *(const float4*)(base + (size_t)m*(3*WIDTH) + WIDTH + c4);
        float4 vv = *(const float4*)(base + (size_t)m*(3*WIDTH) + 2*WIDTH + c4);
        Vs[m][c4+0] = vv.x; Vs[m][c4+1] = vv.y; Vs[m][c4+2] = vv.z; Vs[m][c4+3] = vv.w;
    }
    __syncthreads();

    for (int l = w; l < py; l += 8) {
        qs[w][lane]      = base[(size_t)l*(3*WIDTH) + lane];
        qs[w][lane + 32] = base[(size_t)l*(3*WIDTH) + lane + 32];
        __syncwarp();

        float sloc[2];
        float mx = -1e30f;
        #pragma unroll
        for (int rr = 0; rr < 2; rr++) {
            int m = lane + rr*32;
            float s = -1e30f;
            if (m <= l) {
                float dot = 0.f;
                #pragma unroll
                for (int kk = 0; kk < 16; kk++) {
                    float4 qv = *(const float4*)&qs[w][kk*4];
                    float4 kv = *(const float4*)&Ks[m][kk*4];
                    dot = fmaf(qv.x, kv.x, dot);
                    dot = fmaf(qv.y, kv.y, dot);
                    dot = fmaf(qv.z, kv.z, dot);
                    dot = fmaf(qv.w, kv.w, dot);
                }
                s = dot * 0.125f;
            }
            sloc[rr] = s;
            mx = fmaxf(mx, s);
        }
        #pragma unroll
        for (int o = 16; o; o >>= 1) mx = fmaxf(mx, __shfl_xor_sync(0xffffffffu, mx, o));

        float sum = 0.f;
        #pragma unroll
        for (int rr = 0; rr < 2; rr++) {
            int m = lane + rr*32;
            if (m <= l) {
                float e = __expf(sloc[rr] - mx);
                sc[w][m] = e;
                sum += e;
            }
        }
        #pragma unroll
        for (int o = 16; o; o >>= 1) sum += __shfl_xor_sync(0xffffffffu, sum, o);
        float inv = 1.f / sum;

        float o0 = 0.f, o1 = 0.f;
        for (int m = 0; m <= l; m++) {
            float pm = sc[w][m];
            o0 = fmaf(pm, Vs[m][lane],      o0);
            o1 = fmaf(pm, Vs[m][lane + 32], o1);
        }
        float* op = out + ((size_t)n*SHSTRIDE + l)*WIDTH + h*DHEAD;
        op[lane]      = o0 * inv;
        op[lane + 32] = o1 * inv;
        __syncwarp();
    }
}

// ---------------- attention for prompt windows (per (p,n,h)) ----------------
__launch_bounds__(256)
__global__ void attn_prompt_kernel(const float* __restrict__ qkv,
                                   const int* __restrict__ posy,
                                   float* __restrict__ out)
{
    int bh = blockIdx.x;               // pn*8 + h
    int h = bh & 7, pn = bh >> 3;
    int n = pn & (NSEQ-1);
    int py = posy[n];
    __shared__ __align__(16) float Ks[CTXLEN][68];
    __shared__ __align__(16) float Vs[CTXLEN][65];
    __shared__ __align__(16) float qs[8][64];
    __shared__ __align__(16) float sc[8][80];
    int tid = threadIdx.x, w = tid >> 5, lane = tid & 31;
    const float* shbase = qkv + (size_t)(n*SHSTRIDE)*(3*WIDTH) + h*DHEAD;
    const float* prbase = qkv + ((size_t)SHTOT + (size_t)pn*LPROM)*(3*WIDTH) + h*DHEAD;

    int L = py + LPROM;
    for (int idx = tid; idx < L*16; idx += 256) {
        int m = idx >> 4, c4 = (idx & 15) << 2;
        const float* src = (m < py) ? (shbase + (size_t)m*(3*WIDTH))
                                    : (prbase + (size_t)(m - py)*(3*WIDTH));
        *(float4*)&Ks[m][c4] = *(const float4*)(src + WIDTH + c4);
        float4 vv = *(const float4*)(src + 2*WIDTH + c4);
        Vs[m][c4+0] = vv.x; Vs[m][c4+1] = vv.y; Vs[m][c4+2] = vv.z; Vs[m][c4+3] = vv.w;
    }
    __syncthreads();

    for (int j = w; j < LPROM; j += 8) {
        const float* qrow = prbase + (size_t)j*(3*WIDTH);
        qs[w][lane]      = qrow[lane];
        qs[w][lane + 32] = qrow[lane + 32];
        __syncwarp();

        int klen = py + j + 1;
        float sloc[3];
        float mx = -1e30f;
        #pragma unroll
        for (int rr = 0; rr < 3; rr++) {
            int m = lane + rr*32;
            float s = -1e30f;
            if (m < klen) {
                float dot = 0.f;
                #pragma unroll
                for (int kk = 0; kk < 16; kk++) {
                    float4 qv = *(const float4*)&qs[w][kk*4];
                    float4 kv = *(const float4*)&Ks[m][kk*4];
                    dot = fmaf(qv.x, kv.x, dot);
                    dot = fmaf(qv.y, kv.y, dot);
                    dot = fmaf(qv.z, kv.z, dot);
                    dot = fmaf(qv.w, kv.w, dot);
                }
                s = dot * 0.125f;
            }
            sloc[rr] = s;
            mx = fmaxf(mx, s);
        }
        #pragma unroll
        for (int o = 16; o; o >>= 1) mx = fmaxf(mx, __shfl_xor_sync(0xffffffffu, mx, o));

        float sum = 0.f;
        #pragma unroll
        for (int rr = 0; rr < 3; rr++) {
            int m = lane + rr*32;
            if (m < klen) {
                float e = __expf(sloc[rr] - mx);
                sc[w][m] = e;
                sum += e;
            }
        }
        #pragma unroll
        for (int o = 16; o; o >>= 1) sum += __shfl_xor_sync(0xffffffffu, sum, o);
        float inv = 1.f / sum;

        float o0 = 0.f, o1 = 0.f;
        for (int m = 0; m < klen; m++) {
            float pm = sc[w][m];
            o0 = fmaf(pm, Vs[m][lane],      o0);
            o1 = fmaf(pm, Vs[m][lane + 32], o1);
        }
        float* op = out + ((size_t)SHTOT + (size_t)pn*LPROM + j)*WIDTH + h*DHEAD;
        op[lane]      = o0 * inv;
        op[lane + 32] = o1 * inv;
        __syncwarp();
    }
}

// ---------------- fp32 SGEMM (text projection only) -----
template<bool BT, int EPI>
__launch_bounds__(256)
__global__ void sgemm(const float* __restrict__ A, const float* __restrict__ Bm,
                      const float* __restrict__ bias, const float* __restrict__ res,
                      float* __restrict__ C, int M, int N, int K)
{
    __shared__ __align__(16) float As[16][132];
    __shared__ __align__(16) float Bs[16][132];
    const int tid = threadIdx.x;
    const int m0 = blockIdx.y * 128;
    const int n0 = blockIdx.x * 128;
    const int tm = (tid >> 4) << 3;
    const int tn = (tid & 15) << 3;
    float acc[8][8];
    #pragma unroll
    for (int i = 0; i < 8; i++)
        #pragma unroll
        for (int j = 0; j < 8; j++) acc[i][j] = 0.f;

    for (int k0 = 0; k0 < K; k0 += 16) {
        #pragma unroll
        for (int i = 0; i < 2; i++) {
            int id  = tid + i*256;
            int row = id >> 2;
            int c4  = (id & 3) << 2;
            float4 v = *(const float4*)(A + (size_t)(m0+row)*K + (k0 + c4));
            As[c4+0][row] = v.x; As[c4+1][row] = v.y;
            As[c4+2][row] = v.z; As[c4+3][row] = v.w;
        }
        if (BT) {
            #pragma unroll
            for (int i = 0; i < 2; i++) {
                int id  = tid + i*256;
                int row = id >> 2;
                int c4  = (id & 3) << 2;
                float4 v = *(const float4*)(Bm + (size_t)(n0+row)*K + (k0 + c4));
                Bs[c4+0][row] = v.x; Bs[c4+1][row] = v.y;
                Bs[c4+2][row] = v.z; Bs[c4+3][row] = v.w;
            }
        } else {
            #pragma unroll
            for (int i = 0; i < 2; i++) {
                int id = tid + i*256;
                int kr = id >> 5;
                int nc = (id & 31) << 2;
                float4 v = *(const float4*)(Bm + (size_t)(k0+kr)*N + (n0 + nc));
                *(float4*)(&Bs[kr][nc]) = v;
            }
        }
        __syncthreads();
        #pragma unroll
        for (int kk = 0; kk < 16; kk++) {
            float a[8], bb[8];
            *(float4*)(a)    = *(const float4*)(&As[kk][tm]);
            *(float4*)(a+4)  = *(const float4*)(&As[kk][tm+4]);
            *(float4*)(bb)   = *(const float4*)(&Bs[kk][tn]);
            *(float4*)(bb+4) = *(const float4*)(&Bs[kk][tn+4]);
            #pragma unroll
            for (int i = 0; i < 8; i++)
                #pragma unroll
                for (int j = 0; j < 8; j++)
                    acc[i][j] = fmaf(a[i], bb[j], acc[i][j]);
        }
        __syncthreads();
    }

    float bv[8];
    #pragma unroll
    for (int j = 0; j < 8; j++) bv[j] = bias ? bias[n0+tn+j] : 0.f;
    #pragma unroll
    for (int i = 0; i < 8; i++) {
        size_t off = (size_t)(m0+tm+i)*N + (n0+tn);
        #pragma unroll
        for (int j = 0; j < 8; j++) {
            float v = acc[i][j] + bv[j];
            if (EPI == 1) v = v / (1.f + __expf(-1.702f*v));
            if (EPI == 2) v += res[off + j];
            C[off + j] = v;
        }
    }
}

// ---------------- per-row L2 normalize ----------------
__global__ void normrows_kernel(float* __restrict__ f)
{
    size_t row = blockIdx.x;
    float* r = f + row*EMBED;
    int tid = threadIdx.x;            // 256
    float4 v = *(float4*)(r + tid*4);
    float sq = v.x*v.x + v.y*v.y + v.z*v.z + v.w*v.w;
    __shared__ float sh[8];
    #pragma unroll
    for (int o = 16; o; o >>= 1) sq += __shfl_xor_sync(0xffffffffu, sq, o);
    if ((tid & 31) == 0) sh[tid>>5] = sq;
    __syncthreads();
    float tot = 0.f;
    #pragma unroll
    for (int i = 0; i < 8; i++) tot += sh[i];
    float inv = rsqrtf(tot);
    v.x *= inv; v.y *= inv; v.z *= inv; v.w *= inv;
    *(float4*)(r + tid*4) = v;
}

// ---------------- mean over N, then normalize ------------------------------
__global__ void meannorm_kernel(const float* __restrict__ f, float* __restrict__ out)
{
    int p = blockIdx.x;                // 8
    int tid = threadIdx.x;             // 256
    float4 a = make_float4(0.f, 0.f, 0.f, 0.f);
    for (int n = 0; n < NSEQ; n++) {
        float4 v = *(const float4*)(f + ((size_t)(p*NSEQ+n))*EMBED + tid*4);
        a.x += v.x; a.y += v.y; a.z += v.z; a.w += v.w;
    }
    const float s = 1.f / NSEQ;
    a.x *= s; a.y *= s; a.z *= s; a.w *= s;
    float sq = a.x*a.x + a.y*a.y + a.z*a.z + a.w*a.w;
    __shared__ float sh[8];
    #pragma unroll
    for (int o = 16; o; o >>= 1) sq += __shfl_xor_sync(0xffffffffu, sq, o);
    if ((tid & 31) == 0) sh[tid>>5] = sq;
    __syncthreads();
    float tot = 0.f;
    #pragma unroll
    for (int i = 0; i < 8; i++) tot += sh[i];
    float inv = rsqrtf(tot);
    a.x *= inv; a.y *= inv; a.z *= inv; a.w *= inv;
    *(float4*)(out + (size_t)p*EMBED + tid*4) = a;
}

// ---------------- host orchestration ---------------------------------------
extern "C" void kernel_launch(void* const* d_in, const int* in_sizes, int n_in,
                              void* d_out, int out_size)
{
    const int*   text  = (const int*)  d_in[0];
    const float* cpr   = (const float*)d_in[1];
    const float* tok   = (const float*)d_in[2];
    const float* pos   = (const float*)d_in[3];
    const float* qkv_w = (const float*)d_in[4];
    const float* qkv_b = (const float*)d_in[5];
    const float* out_w = (const float*)d_in[6];
    const float* out_b = (const float*)d_in[7];
    const float* ln1_w = (const float*)d_in[8];
    const float* ln1_b = (const float*)d_in[9];
    const float* ln2_w = (const float*)d_in[10];
    const float* ln2_b = (const float*)d_in[11];
    const float* fc_w  = (const float*)d_in[12];
    const float* fc_b  = (const float*)d_in[13];
    const float* pj_w  = (const float*)d_in[14];
    const float* pj_b  = (const float*)d_in[15];
    const float* lnf_w = (const float*)d_in[16];
    const float* lnf_b = (const float*)d_in[17];
    const float* tproj = (const float*)d_in[18];
    float* outp = (float*)d_out;
    (void)in_sizes; (void)n_in; (void)out_size;

    void* pv;
    cudaGetSymbolAddress(&pv, g_h);    float* h    = (float*)pv;
    cudaGetSymbolAddress(&pv, g_y);    float* y    = (float*)pv;
    cudaGetSymbolAddress(&pv, g_attn); float* attn = (float*)pv;
    cudaGetSymbolAddress(&pv, g_qkv);  float* qkv  = (float*)pv;
    cudaGetSymbolAddress(&pv, g_ffn);  float* ffn  = (float*)pv;
    cudaGetSymbolAddress(&pv, g_posy); int*   posy = (int*)pv;
    cudaGetSymbolAddress(&pv, g_fy);   float* fy   = (float*)pv;
    cudaGetSymbolAddress(&pv, g_feats);float* fts  = (float*)pv;

    cudaFuncSetAttribute(mma_gemm<0>, cudaFuncAttributeMaxDynamicSharedMemorySize, MMA_SMEM_BYTES);
    cudaFuncSetAttribute(mma_gemm<1>, cudaFuncAttributeMaxDynamicSharedMemorySize, MMA_SMEM_BYTES);
    cudaFuncSetAttribute(mma_gemm<2>, cudaFuncAttributeMaxDynamicSharedMemorySize, MMA_SMEM_BYTES);

    posy_kernel<<<1, 128>>>(text, posy);
    embed_kernel<<<MTOT, 128>>>(text, cpr, tok, pos, posy, h);

    const int GY = MTOT/128;               // 189
    for (int L = 0; L < LAYERS; L++) {
        const float* qw = qkv_w + (size_t)L*3*WIDTH*WIDTH;
        const float* qb = qkv_b + (size_t)L*3*WIDTH;
        const float* ow = out_w + (size_t)L*WIDTH*WIDTH;
        const float* ob = out_b + (size_t)L*WIDTH;
        const float* fw = fc_w  + (size_t)L*4*WIDTH*WIDTH;
        const float* fb = fc_b  + (size_t)L*4*WIDTH;
        const float* pw = pj_w  + (size_t)L*WIDTH*4*WIDTH;
        const float* pb = pj_b  + (size_t)L*WIDTH;

        ln_kernel<<<MTOT, 128>>>(h, ln1_w + L*WIDTH, ln1_b + L*WIDTH, y);
        mma_gemm<0><<<dim3(3*WIDTH/128, GY), 256, MMA_SMEM_BYTES>>>(
            y, qw, qb, nullptr, qkv, MTOT, 3*WIDTH, WIDTH);
        attn_prefix_kernel<<<NSEQ*HEADS, 256>>>(qkv, posy, attn);
        attn_prompt_kernel<<<BATCH*HEADS, 256>>>(qkv, posy, attn);
        mma_gemm<2><<<dim3(WIDTH/128, GY), 256, MMA_SMEM_BYTES>>>(
            attn, ow, ob, h, h, MTOT, WIDTH, WIDTH);
        ln_kernel<<<MTOT, 128>>>(h, ln2_w + L*WIDTH, ln2_b + L*WIDTH, y);
        mma_gemm<1><<<dim3(4*WIDTH/128, GY), 256, MMA_SMEM_BYTES>>>(
            y, fw, fb, nullptr, ffn, MTOT, 4*WIDTH, WIDTH);
        mma_gemm<2><<<dim3(WIDTH/128, GY), 256, MMA_SMEM_BYTES>>>(
            ffn, pw, pb, h, h, MTOT, WIDTH, 4*WIDTH);
    }

    gatherln_kernel<<<BATCH, 128>>>(h, lnf_w, lnf_b, fy);
    sgemm<false,0><<<dim3(EMBED/128, BATCH/128), 256>>>(
        fy, tproj, nullptr, nullptr, fts, BATCH, EMBED, WIDTH);
    normrows_kernel<<<BATCH, 256>>>(fts);
    meannorm_kernel<<<PPROMPT, 256>>>(fts, outp);
}

// round 17
// speedup vs baseline: 1.0918x; 1.0592x over previous
#include <cuda_runtime.h>
#include <cuda_bf16.h>
#include <cstdint>
#include <cstddef>

// ---------------- problem constants ----------------
#define CTXLEN 77
#define WIDTH  512
#define HEADS  8
#define DHEAD  64
#define LAYERS 12
#define EMBED  1024
#define NSEQ   128
#define PPROMPT 8
#define LPROM  16
#define EOTTOK 49407
#define BATCH  (PPROMPT*NSEQ)          /* 1024 */

// compacted layout: shared prefix (computed once across P) + prompt windows
#define SHSTRIDE 61
#define SHTOT (NSEQ*SHSTRIDE)          /* 7808  */
#define PRTOT (BATCH*LPROM)            /* 16384 */
#define MTOT  (SHTOT+PRTOT)            /* 24192 = 189*128 */

// ---------------- device scratch ----------------
__device__ float g_h   [(size_t)MTOT*WIDTH];
__device__ float g_y   [(size_t)MTOT*WIDTH];
__device__ float g_attn[(size_t)MTOT*WIDTH];
__device__ float g_qkv [(size_t)MTOT*3*WIDTH];
__device__ float g_ffn [(size_t)MTOT*4*WIDTH];
__device__ int   g_posy[NSEQ];
__device__ float g_fy  [(size_t)BATCH*WIDTH];
__device__ float g_feats[(size_t)BATCH*EMBED];
// final-layer compact buffers (feature rows only)
__device__ float g_hc  [(size_t)BATCH*WIDTH];
__device__ float g_yc  [(size_t)BATCH*WIDTH];
__device__ float g_attc[(size_t)BATCH*WIDTH];
__device__ float g_ffnc[(size_t)BATCH*4*WIDTH];

// ================= helpers =================
__device__ __forceinline__ uint32_t smem_u32(const void* p) {
    uint32_t a;
    asm("{ .reg .u64 t; cvta.to.shared.u64 t, %1; cvt.u32.u64 %0, t; }" : "=r"(a) : "l"(p));
    return a;
}
__device__ __forceinline__ void cp_async16(uint32_t s, const void* g) {
    asm volatile("cp.async.cg.shared.global [%0], [%1], 16;" :: "r"(s), "l"(g));
}
#define CP_COMMIT() asm volatile("cp.async.commit_group;" ::: "memory")

__device__ __forceinline__ void mma_tf32(float* d, const uint32_t* a, const uint32_t* b) {
    asm volatile(
        "mma.sync.aligned.m16n8k8.row.col.f32.tf32.tf32.f32 "
        "{%0,%1,%2,%3}, {%4,%5,%6,%7}, {%8,%9}, {%0,%1,%2,%3};"
        : "+f"(d[0]), "+f"(d[1]), "+f"(d[2]), "+f"(d[3])
        : "r"(a[0]), "r"(a[1]), "r"(a[2]), "r"(a[3]), "r"(b[0]), "r"(b[1]));
}

// ================= mma.sync tf32 GEMM (R7 config, frozen) ===================
#define ROWSTRIDE 40
#define TILEF (128*ROWSTRIDE)
#define STAGEF (2*TILEF)
#define MMA_SMEM_BYTES (2*STAGEF*4)    /* 81920 bytes */

template<int EPI>
__launch_bounds__(256, 2)
__global__ void mma_gemm(const float* __restrict__ A, const float* __restrict__ B,
                         const float* __restrict__ bias, const float* __restrict__ res,
                         float* __restrict__ C, int M, int N, int K)
{
    extern __shared__ __align__(16) float sm[];
    const int tid  = threadIdx.x;
    const int lane = tid & 31, wid = tid >> 5;
    const int wm = wid & 1, wn = wid >> 1;     // 2 x 4 warps, 64x32 each
    const int m0 = blockIdx.y * 128, n0 = blockIdx.x * 128;
    const uint32_t sbase = smem_u32(sm);

    auto stage = [&](int s, int k0) {
        #pragma unroll
        for (int i = 0; i < 4; i++) {
            int ch  = tid + i*256;
            int row = ch >> 3;
            int cc  = (ch & 7) << 2;
            uint32_t so = sbase + (uint32_t)(s*STAGEF + row*ROWSTRIDE + cc)*4u;
            cp_async16(so,            A + (size_t)(m0+row)*K + k0 + cc);
            cp_async16(so + TILEF*4u, B + (size_t)(n0+row)*K + k0 + cc);
        }
        CP_COMMIT();
    };

    float acc[4][4][4];
    #pragma unroll
    for (int mt = 0; mt < 4; mt++)
        #pragma unroll
        for (int nt = 0; nt < 4; nt++)
            #pragma unroll
            for (int q = 0; q < 4; q++) acc[mt][nt][q] = 0.f;

    const int nk = K >> 5;
    stage(0, 0);
    stage(1, 32);

    const int r = lane >> 2, c = lane & 3;
    for (int i = 0; i < nk; i++) {
        if (i == nk - 1) asm volatile("cp.async.wait_group 0;" ::: "memory");
        else             asm volatile("cp.async.wait_group 1;" ::: "memory");
        __syncthreads();
        const float* As = sm + (i & 1)*STAGEF;
        const float* Bs = As + TILEF;
        #pragma unroll
        for (int ks = 0; ks < 4; ks++) {
            uint32_t a[4][4], b[4][2];
            #pragma unroll
            for (int mt = 0; mt < 4; mt++) {
                const float* p0 = As + (wm*64 + mt*16 + r)*ROWSTRIDE + ks*8 + 2*c;
                float2 v0 = *(const float2*)p0;
                float2 v1 = *(const float2*)(p0 + 8*ROWSTRIDE);
                a[mt][0] = __float_as_uint(v0.x);
                a[mt][2] = __float_as_uint(v0.y);
                a[mt][1] = __float_as_uint(v1.x);
                a[mt][3] = __float_as_uint(v1.y);
            }
            #pragma unroll
            for (int nt = 0; nt < 4; nt++) {
                const float* p = Bs + (wn*32 + nt*8 + r)*ROWSTRIDE + ks*8 + 2*c;
                float2 v = *(const float2*)p;
                b[nt][0] = __float_as_uint(v.x);
                b[nt][1] = __float_as_uint(v.y);
            }
            #pragma unroll
            for (int mt = 0; mt < 4; mt++)
                #pragma unroll
                for (int nt = 0; nt < 4; nt++)
                    mma_tf32(acc[mt][nt], a[mt], b[nt]);
        }
        __syncthreads();
        if (i + 2 < nk) stage(i & 1, (i + 2)*32);
    }

    #pragma unroll
    for (int mt = 0; mt < 4; mt++) {
        int row0 = m0 + wm*64 + mt*16 + r;
        #pragma unroll
        for (int nt = 0; nt < 4; nt++) {
            int col = n0 + wn*32 + nt*8 + 2*c;
            float b0 = bias[col], b1 = bias[col + 1];
            float2 v0, v1;
            v0.x = acc[mt][nt][0] + b0; v0.y = acc[mt][nt][1] + b1;
            v1.x = acc[mt][nt][2] + b0; v1.y = acc[mt][nt][3] + b1;
            if (EPI == 1) {
                v0.x = v0.x / (1.f + __expf(-1.702f*v0.x));
                v0.y = v0.y / (1.f + __expf(-1.702f*v0.y));
                v1.x = v1.x / (1.f + __expf(-1.702f*v1.x));
                v1.y = v1.y / (1.f + __expf(-1.702f*v1.y));
            }
            if (EPI == 2) {
                float2 r0 = *(const float2*)(res + (size_t)row0*N + col);
                float2 r1 = *(const float2*)(res + (size_t)(row0+8)*N + col);
                v0.x += r0.x; v0.y += r0.y; v1.x += r1.x; v1.y += r1.y;
            }
            *(float2*)(C + (size_t)row0*N + col)     = v0;
            *(float2*)(C + (size_t)(row0+8)*N + col) = v1;
        }
    }
}

// ---------------- pos_y ----------------
__global__ void posy_kernel(const int* __restrict__ text, int* __restrict__ posy)
{
    int n = threadIdx.x;
    if (n < NSEQ) {
        int p = 0;
        for (int t = 0; t < CTXLEN; t++) {
            if (text[n*CTXLEN + t] == EOTTOK) { p = t; break; }
        }
        posy[n] = p;
    }
}

// ---------------- embedding into the compacted layout ----------------
__global__ void embed_kernel(const int* __restrict__ text,
                             const float* __restrict__ cprompt,
                             const float* __restrict__ tok,
                             const float* __restrict__ pos,
                             const int* __restrict__ posy,
                             float* __restrict__ h)
{
    int row = blockIdx.x;
    int d = threadIdx.x * 4;
    float4 v;
    if (row < SHTOT) {
        int n = row / SHSTRIDE, t = row % SHSTRIDE;
        int py = posy[n];
        if (t >= py) {
            *(float4*)(h + (size_t)row*WIDTH + d) = make_float4(0.f,0.f,0.f,0.f);
            return;
        }
        const float* src = tok + (size_t)text[n*CTXLEN + t]*WIDTH;
        float4 s = *(const float4*)(src + d);
        float4 pe = *(const float4*)(pos + (size_t)t*WIDTH + d);
        v.x = s.x + pe.x; v.y = s.y + pe.y; v.z = s.z + pe.z; v.w = s.w + pe.w;
    } else {
        int q = row - SHTOT;
        int j = q & (LPROM-1), pn = q >> 4;
        int p = pn >> 7, n = pn & (NSEQ-1);
        int t = posy[n] + j;
        float4 s = *(const float4*)(cprompt + ((size_t)p*LPROM + j)*WIDTH + d);
        float4 pe = *(const float4*)(pos + (size_t)t*WIDTH + d);
        v.x = s.x + pe.x; v.y = s.y + pe.y; v.z = s.z + pe.z; v.w = s.w + pe.w;
    }
    *(float4*)(h + (size_t)row*WIDTH + d) = v;
}

// ---------------- layernorm ----------------
__device__ __forceinline__ void ln_row(const float* __restrict__ xr,
                                       const float* __restrict__ w,
                                       const float* __restrict__ b,
                                       float* __restrict__ yr)
{
    int tid = threadIdx.x;               // 128
    float4 v = *(const float4*)(xr + tid*4);
    float s  = v.x + v.y + v.z + v.w;
    float sq = v.x*v.x + v.y*v.y + v.z*v.z + v.w*v.w;
    __shared__ float rs[4], rq[4];
    #pragma unroll
    for (int o = 16; o; o >>= 1) {
        s  += __shfl_xor_sync(0xffffffffu, s,  o);
        sq += __shfl_xor_sync(0xffffffffu, sq, o);
    }
    if ((tid & 31) == 0) { rs[tid>>5] = s; rq[tid>>5] = sq; }
    __syncthreads();
    s  = rs[0]+rs[1]+rs[2]+rs[3];
    sq = rq[0]+rq[1]+rq[2]+rq[3];
    float mean = s * (1.f/WIDTH);
    float var  = sq * (1.f/WIDTH) - mean*mean;
    float rstd = rsqrtf(var + 1e-5f);
    float4 wv = *(const float4*)(w + tid*4);
    float4 bv = *(const float4*)(b + tid*4);
    float4 o;
    o.x = (v.x-mean)*rstd*wv.x + bv.x;
    o.y = (v.y-mean)*rstd*wv.y + bv.y;
    o.z = (v.z-mean)*rstd*wv.z + bv.z;
    o.w = (v.w-mean)*rstd*wv.w + bv.w;
    *(float4*)(yr + tid*4) = o;
}

__global__ void ln_kernel(const float* __restrict__ x, const float* __restrict__ w,
                          const float* __restrict__ b, float* __restrict__ y)
{
    size_t row = blockIdx.x;
    ln_row(x + row*WIDTH, w, b, y + row*WIDTH);
}

// gather h feature rows into compact buffer (1024 x 512)
__global__ void gatherh_kernel(const float* __restrict__ h, float* __restrict__ hc)
{
    int bn = blockIdx.x;
    size_t row = (size_t)SHTOT + (size_t)bn*LPROM + (LPROM - 1);
    int d = threadIdx.x * 4;
    *(float4*)(hc + (size_t)bn*WIDTH + d) = *(const float4*)(h + row*WIDTH + d);
}

// ---------------- attention over the shared prefix (per (n,h)) -------------
__launch_bounds__(256)
__global__ void attn_prefix_kernel(const float* __restrict__ qkv,
                                   const int* __restrict__ posy,
                                   float* __restrict__ out)
{
    int bh = blockIdx.x;               // n*8 + h
    int h = bh & 7, n = bh >> 3;
    int py = posy[n];
    __shared__ __align__(16) float Ks[SHSTRIDE][68];
    __shared__ __align__(16) float Vs[SHSTRIDE][65];
    __shared__ __align__(16) float qs[8][64];
    __shared__ __align__(16) float sc[8][64];
    int tid = threadIdx.x, w = tid >> 5, lane = tid & 31;
    const float* base = qkv + (size_t)(n*SHSTRIDE)*(3*WIDTH) + h*DHEAD;

    for (int idx = tid; idx < py*16; idx += 256) {
        int m = idx >> 4, c4 = (idx & 15) << 2;
        *(float4*)&Ks[m][c4] = *(const float4*)(base + (size_t)m*(3*WIDTH) + WIDTH + c4);
        float4 vv = *(const float4*)(base + (size_t)m*(3*WIDTH) + 2*WIDTH + c4);
        Vs[m][c4+0] = vv.x; Vs[m][c4+1] = vv.y; Vs[m][c4+2] = vv.z; Vs[m][c4+3] = vv.w;
    }
    __syncthreads();

    for (int l = w; l < py; l += 8) {
        qs[w][lane]      = base[(size_t)l*(3*WIDTH) + lane];
        qs[w][lane + 32] = base[(size_t)l*(3*WIDTH) + lane + 32];
        __syncwarp();

        float sloc[2];
        float mx = -1e30f;
        #pragma unroll
        for (int rr = 0; rr < 2; rr++) {
            int m = lane + rr*32;
            float s = -1e30f;
            if (m <= l) {
                float dot = 0.f;
                #pragma unroll
                for (int kk = 0; kk < 16; kk++) {
                    float4 qv = *(const float4*)&qs[w][kk*4];
                    float4 kv = *(const float4*)&Ks[m][kk*4];
                    dot = fmaf(qv.x, kv.x, dot);
                    dot = fmaf(qv.y, kv.y, dot);
                    dot = fmaf(qv.z, kv.z, dot);
                    dot = fmaf(qv.w, kv.w, dot);
                }
                s = dot * 0.125f;
            }
            sloc[rr] = s;
            mx = fmaxf(mx, s);
        }
        #pragma unroll
        for (int o = 16; o; o >>= 1) mx = fmaxf(mx, __shfl_xor_sync(0xffffffffu, mx, o));

        float sum = 0.f;
        #pragma unroll
        for (int rr = 0; rr < 2; rr++) {
            int m = lane + rr*32;
            if (m <= l) {
                float e = __expf(sloc[rr] - mx);
                sc[w][m] = e;
                sum += e;
            }
        }
        #pragma unroll
        for (int o = 16; o; o >>= 1) sum += __shfl_xor_sync(0xffffffffu, sum, o);
        float inv = 1.f / sum;

        float o0 = 0.f, o1 = 0.f;
        for (int m = 0; m <= l; m++) {
            float pm = sc[w][m];
            o0 = fmaf(pm, Vs[m][lane],      o0);
            o1 = fmaf(pm, Vs[m][lane + 32], o1);
        }
        float* op = out + ((size_t)n*SHSTRIDE + l)*WIDTH + h*DHEAD;
        op[lane]      = o0 * inv;
        op[lane + 32] = o1 * inv;
        __syncwarp();
    }
}

// ---------------- attention for prompt windows (per (p,n,h)) ----------------
// QLAST=0: all 16 prompt queries, outputs to compacted layout rows.
// QLAST=1: only the feature query j=LP-1, output to compact [pn] row buffer.
template<int QLAST>
__launch_bounds__(256)
__global__ void attn_prompt_kernel(const float* __restrict__ qkv,
                                   const int* __restrict__ posy,
                                   float* __restrict__ out)
{
    int bh = blockIdx.x;               // pn*8 + h
    int h = bh & 7, pn = bh >> 3;
    int n = pn & (NSEQ-1);
    int py = posy[n];
    __shared__ __align__(16) float Ks[CTXLEN][68];
    __shared__ __align__(16) float Vs[CTXLEN][65];
    __shared__ __align__(16) float qs[8][64];
    __shared__ __align__(16) float sc[8][80];
    int tid = threadIdx.x, w = tid >> 5, lane = tid & 31;
    const float* shbase = qkv + (size_t)(n*SHSTRIDE)*(3*WIDTH) + h*DHEAD;
    const float* prbase = qkv + ((size_t)SHTOT + (size_t)pn*LPROM)*(3*WIDTH) + h*DHEAD;

    int L = py + LPROM;
    for (int idx = tid; idx < L*16; idx += 256) {
        int m = idx >> 4, c4 = (idx & 15) << 2;
        const float* src = (m < py) ? (shbase + (size_t)m*(3*WIDTH))
                                    : (prbase + (size_t)(m - py)*(3*WIDTH));
        *(float4*)&Ks[m][c4] = *(const float4*)(src + WIDTH + c4);
        float4 vv = *(const float4*)(src + 2*WIDTH + c4);
        Vs[m][c4+0] = vv.x; Vs[m][c4+1] = vv.y; Vs[m][c4+2] = vv.z; Vs[m][c4+3] = vv.w;
    }
    __syncthreads();

    const int jbeg = QLAST ? (LPROM-1) : 0;
    for (int j = jbeg + (QLAST ? 0 : w); j < LPROM; j += (QLAST ? LPROM : 8)) {
        if (QLAST && w != 0) break;     // single query: warp 0 only
        const float* qrow = prbase + (size_t)j*(3*WIDTH);
        qs[w][lane]      = qrow[lane];
        qs[w][lane + 32] = qrow[lane + 32];
        __syncwarp();

        int klen = py + j + 1;
        float sloc[3];
        float mx = -1e30f;
        #pragma unroll
        for (int rr = 0; rr < 3; rr++) {
            int m = lane + rr*32;
            float s = -1e30f;
            if (m < klen) {
                float dot = 0.f;
                #pragma unroll
                for (int kk = 0; kk < 16; kk++) {
                    float4 qv = *(const float4*)&qs[w][kk*4];
                    float4 kv = *(const float4*)&Ks[m][kk*4];
                    dot = fmaf(qv.x, kv.x, dot);
                    dot = fmaf(qv.y, kv.y, dot);
                    dot = fmaf(qv.z, kv.z, dot);
                    dot = fmaf(qv.w, kv.w, dot);
                }
                s = dot * 0.125f;
            }
            sloc[rr] = s;
            mx = fmaxf(mx, s);
        }
        #pragma unroll
        for (int o = 16; o; o >>= 1) mx = fmaxf(mx, __shfl_xor_sync(0xffffffffu, mx, o));

        float sum = 0.f;
        #pragma unroll
        for (int rr = 0; rr < 3; rr++) {
            int m = lane + rr*32;
            if (m < klen) {
                float e = __expf(sloc[rr] - mx);
                sc[w][m] = e;
                sum += e;
            }
        }
        #pragma unroll
        for (int o = 16; o; o >>= 1) sum += __shfl_xor_sync(0xffffffffu, sum, o);
        float inv = 1.f / sum;

        float o0 = 0.f, o1 = 0.f;
        for (int m = 0; m < klen; m++) {
            float pm = sc[w][m];
            o0 = fmaf(pm, Vs[m][lane],      o0);
            o1 = fmaf(pm, Vs[m][lane + 32], o1);
        }
        float* op = QLAST
            ? (out + (size_t)pn*WIDTH + h*DHEAD)
            : (out + ((size_t)SHTOT + (size_t)pn*LPROM + j)*WIDTH + h*DHEAD);
        op[lane]      = o0 * inv;
        op[lane + 32] = o1 * inv;
        __syncwarp();
    }
}

// ---------------- fp32 SGEMM (text projection only) -----
template<bool BT, int EPI>
__launch_bounds__(256)
__global__ void sgemm(const float* __restrict__ A, const float* __restrict__ Bm,
                      const float* __restrict__ bias, const float* __restrict__ res,
                      float* __restrict__ C, int M, int N, int K)
{
    __shared__ __align__(16) float As[16][132];
    __shared__ __align__(16) float Bs[16][132];
    const int tid = threadIdx.x;
    const int m0 = blockIdx.y * 128;
    const int n0 = blockIdx.x * 128;
    const int tm = (tid >> 4) << 3;
    const int tn = (tid & 15) << 3;
    float acc[8][8];
    #pragma unroll
    for (int i = 0; i < 8; i++)
        #pragma unroll
        for (int j = 0; j < 8; j++) acc[i][j] = 0.f;

    for (int k0 = 0; k0 < K; k0 += 16) {
        #pragma unroll
        for (int i = 0; i < 2; i++) {
            int id  = tid + i*256;
            int row = id >> 2;
            int c4  = (id & 3) << 2;
            float4 v = *(const float4*)(A + (size_t)(m0+row)*K + (k0 + c4));
            As[c4+0][row] = v.x; As[c4+1][row] = v.y;
            As[c4+2][row] = v.z; As[c4+3][row] = v.w;
        }
        if (BT) {
            #pragma unroll
            for (int i = 0; i < 2; i++) {
                int id  = tid + i*256;
                int row = id >> 2;
                int c4  = (id & 3) << 2;
                float4 v = *(const float4*)(Bm + (size_t)(n0+row)*K + (k0 + c4));
                Bs[c4+0][row] = v.x; Bs[c4+1][row] = v.y;
                Bs[c4+2][row] = v.z; Bs[c4+3][row] = v.w;
            }
        } else {
            #pragma unroll
            for (int i = 0; i < 2; i++) {
                int id = tid + i*256;
                int kr = id >> 5;
                int nc = (id & 31) << 2;
                float4 v = *(const float4*)(Bm + (size_t)(k0+kr)*N + (n0 + nc));
                *(float4*)(&Bs[kr][nc]) = v;
            }
        }
        __syncthreads();
        #pragma unroll
        for (int kk = 0; kk < 16; kk++) {
            float a[8], bb[8];
            *(float4*)(a)    = *(const float4*)(&As[kk][tm]);
            *(float4*)(a+4)  = *(const float4*)(&As[kk][tm+4]);
            *(float4*)(bb)   = *(const float4*)(&Bs[kk][tn]);
            *(float4*)(bb+4) = *(const float4*)(&Bs[kk][tn+4]);
            #pragma unroll
            for (int i = 0; i < 8; i++)
                #pragma unroll
                for (int j = 0; j < 8; j++)
                    acc[i][j] = fmaf(a[i], bb[j], acc[i][j]);
        }
        __syncthreads();
    }

    float bv[8];
    #pragma unroll
    for (int j = 0; j < 8; j++) bv[j] = bias ? bias[n0+tn+j] : 0.f;
    #pragma unroll
    for (int i = 0; i < 8; i++) {
        size_t off = (size_t)(m0+tm+i)*N + (n0+tn);
        #pragma unroll
        for (int j = 0; j < 8; j++) {
            float v = acc[i][j] + bv[j];
            if (EPI == 1) v = v / (1.f + __expf(-1.702f*v));
            if (EPI == 2) v += res[off + j];
            C[off + j] = v;
        }
    }
}

// ---------------- per-row L2 normalize ----------------
__global__ void normrows_kernel(float* __restrict__ f)
{
    size_t row = blockIdx.x;
    float* r = f + row*EMBED;
    int tid = threadIdx.x;            // 256
    float4 v = *(float4*)(r + tid*4);
    float sq = v.x*v.x + v.y*v.y + v.z*v.z + v.w*v.w;
    __shared__ float sh[8];
    #pragma unroll
    for (int o = 16; o; o >>= 1) sq += __shfl_xor_sync(0xffffffffu, sq, o);
    if ((tid & 31) == 0) sh[tid>>5] = sq;
    __syncthreads();
    float tot = 0.f;
    #pragma unroll
    for (int i = 0; i < 8; i++) tot += sh[i];
    float inv = rsqrtf(tot);
    v.x *= inv; v.y *= inv; v.z *= inv; v.w *= inv;
    *(float4*)(r + tid*4) = v;
}

// ---------------- mean over N, then normalize ------------------------------
__global__ void meannorm_kernel(const float* __restrict__ f, float* __restrict__ out)
{
    int p = blockIdx.x;                // 8
    int tid = threadIdx.x;             // 256
    float4 a = make_float4(0.f, 0.f, 0.f, 0.f);
    for (int n = 0; n < NSEQ; n++) {
        float4 v = *(const float4*)(f + ((size_t)(p*NSEQ+n))*EMBED + tid*4);
        a.x += v.x; a.y += v.y; a.z += v.z; a.w += v.w;
    }
    const float s = 1.f / NSEQ;
    a.x *= s; a.y *= s; a.z *= s; a.w *= s;
    float sq = a.x*a.x + a.y*a.y + a.z*a.z + a.w*a.w;
    __shared__ float sh[8];
    #pragma unroll
    for (int o = 16; o; o >>= 1) sq += __shfl_xor_sync(0xffffffffu, sq, o);
    if ((tid & 31) == 0) sh[tid>>5] = sq;
    __syncthreads();
    float tot = 0.f;
    #pragma unroll
    for (int i = 0; i < 8; i++) tot += sh[i];
    float inv = rsqrtf(tot);
    a.x *= inv; a.y *= inv; a.z *= inv; a.w *= inv;
    *(float4*)(out + (size_t)p*EMBED + tid*4) = a;
}

// ---------------- host orchestration ---------------------------------------
extern "C" void kernel_launch(void* const* d_in, const int* in_sizes, int n_in,
                              void* d_out, int out_size)
{
    const int*   text  = (const int*)  d_in[0];
    const float* cpr   = (const float*)d_in[1];
    const float* tok   = (const float*)d_in[2];
    const float* pos   = (const float*)d_in[3];
    const float* qkv_w = (const float*)d_in[4];
    const float* qkv_b = (const float*)d_in[5];
    const float* out_w = (const float*)d_in[6];
    const float* out_b = (const float*)d_in[7];
    const float* ln1_w = (const float*)d_in[8];
    const float* ln1_b = (const float*)d_in[9];
    const float* ln2_w = (const float*)d_in[10];
    const float* ln2_b = (const float*)d_in[11];
    const float* fc_w  = (const float*)d_in[12];
    const float* fc_b  = (const float*)d_in[13];
    const float* pj_w  = (const float*)d_in[14];
    const float* pj_b  = (const float*)d_in[15];
    const float* lnf_w = (const float*)d_in[16];
    const float* lnf_b = (const float*)d_in[17];
    const float* tproj = (const float*)d_in[18];
    float* outp = (float*)d_out;
    (void)in_sizes; (void)n_in; (void)out_size;

    void* pv;
    cudaGetSymbolAddress(&pv, g_h);    float* h    = (float*)pv;
    cudaGetSymbolAddress(&pv, g_y);    float* y    = (float*)pv;
    cudaGetSymbolAddress(&pv, g_attn); float* attn = (float*)pv;
    cudaGetSymbolAddress(&pv, g_qkv);  float* qkv  = (float*)pv;
    cudaGetSymbolAddress(&pv, g_ffn);  float* ffn  = (float*)pv;
    cudaGetSymbolAddress(&pv, g_posy); int*   posy = (int*)pv;
    cudaGetSymbolAddress(&pv, g_fy);   float* fy   = (float*)pv;
    cudaGetSymbolAddress(&pv, g_feats);float* fts  = (float*)pv;
    cudaGetSymbolAddress(&pv, g_hc);   float* hc   = (float*)pv;
    cudaGetSymbolAddress(&pv, g_yc);   float* yc   = (float*)pv;
    cudaGetSymbolAddress(&pv, g_attc); float* attc = (float*)pv;
    cudaGetSymbolAddress(&pv, g_ffnc); float* ffnc = (float*)pv;

    cudaFuncSetAttribute(mma_gemm<0>, cudaFuncAttributeMaxDynamicSharedMemorySize, MMA_SMEM_BYTES);
    cudaFuncSetAttribute(mma_gemm<1>, cudaFuncAttributeMaxDynamicSharedMemorySize, MMA_SMEM_BYTES);
    cudaFuncSetAttribute(mma_gemm<2>, cudaFuncAttributeMaxDynamicSharedMemorySize, MMA_SMEM_BYTES);

    posy_kernel<<<1, 128>>>(text, posy);
    embed_kernel<<<MTOT, 128>>>(text, cpr, tok, pos, posy, h);

    const int GY = MTOT/128;               // 189
    for (int L = 0; L < LAYERS; L++) {
        const float* qw = qkv_w + (size_t)L*3*WIDTH*WIDTH;
        const float* qb = qkv_b + (size_t)L*3*WIDTH;
        const float* ow = out_w + (size_t)L*WIDTH*WIDTH;
        const float* ob = out_b + (size_t)L*WIDTH;
        const float* fw = fc_w  + (size_t)L*4*WIDTH*WIDTH;
        const float* fb = fc_b  + (size_t)L*4*WIDTH;
        const float* pw = pj_w  + (size_t)L*WIDTH*4*WIDTH;
        const float* pb = pj_b  + (size_t)L*WIDTH;

        if (L < LAYERS-1) {
            ln_kernel<<<MTOT, 128>>>(h, ln1_w + L*WIDTH, ln1_b + L*WIDTH, y);
            mma_gemm<0><<<dim3(3*WIDTH/128, GY), 256, MMA_SMEM_BYTES>>>(
                y, qw, qb, nullptr, qkv, MTOT, 3*WIDTH, WIDTH);
            attn_prefix_kernel<<<NSEQ*HEADS, 256>>>(qkv, posy, attn);
            attn_prompt_kernel<0><<<BATCH*HEADS, 256>>>(qkv, posy, attn);
            mma_gemm<2><<<dim3(WIDTH/128, GY), 256, MMA_SMEM_BYTES>>>(
                attn, ow, ob, h, h, MTOT, WIDTH, WIDTH);
            ln_kernel<<<MTOT, 128>>>(h, ln2_w + L*WIDTH, ln2_b + L*WIDTH, y);
            mma_gemm<1><<<dim3(4*WIDTH/128, GY), 256, MMA_SMEM_BYTES>>>(
                y, fw, fb, nullptr, ffn, MTOT, 4*WIDTH, WIDTH);
            mma_gemm<2><<<dim3(WIDTH/128, GY), 256, MMA_SMEM_BYTES>>>(
                ffn, pw, pb, h, h, MTOT, WIDTH, 4*WIDTH);
        } else {
            // FINAL LAYER: only the 1024 feature rows influence the output.
            ln_kernel<<<MTOT, 128>>>(h, ln1_w + L*WIDTH, ln1_b + L*WIDTH, y);
            mma_gemm<0><<<dim3(3*WIDTH/128, GY), 256, MMA_SMEM_BYTES>>>(
                y, qw, qb, nullptr, qkv, MTOT, 3*WIDTH, WIDTH);   // full K/V needed
            attn_prompt_kernel<1><<<BATCH*HEADS, 256>>>(qkv, posy, attc);
            gatherh_kernel<<<BATCH, 128>>>(h, hc);
            mma_gemm<2><<<dim3(WIDTH/128, BATCH/128), 256, MMA_SMEM_BYTES>>>(
                attc, ow, ob, hc, hc, BATCH, WIDTH, WIDTH);
            ln_kernel<<<BATCH, 128>>>(hc, ln2_w + L*WIDTH, ln2_b + L*WIDTH, yc);
            mma_gemm<1><<<dim3(4*WIDTH/128, BATCH/128), 256, MMA_SMEM_BYTES>>>(
                yc, fw, fb, nullptr, ffnc, BATCH, 4*WIDTH, WIDTH);
            mma_gemm<2><<<dim3(WIDTH/128, BATCH/128), 256, MMA_SMEM_BYTES>>>(
                ffnc, pw, pb, hc, hc, BATCH, WIDTH, 4*WIDTH);
        }
    }

    // final LN (lnf) on compact feature rows
    ln_kernel<<<BATCH, 128>>>(hc, lnf_w, lnf_b, fy);
    sgemm<false,0><<<dim3(EMBED/128, BATCH/128), 256>>>(
        fy, tproj, nullptr, nullptr, fts, BATCH, EMBED, WIDTH);
    normrows_kernel<<<BATCH, 256>>>(fts);
    meannorm_kernel<<<PPROMPT, 256>>>(fts, outp);
}